// round 10
// baseline (speedup 1.0000x reference)
#include <cuda_runtime.h>
#include <cstdint>

#define L_SEQ   2048
#define D_DIM   512
#define B_BATCH 32
#define M_ROWS  (B_BATCH * L_SEQ)   /* 65536 */
#define K_DIM   1024
#define N_DIM   512

// ---------------- scratch (static device globals: no allocation) ----------------
__device__ float g_ycat[(size_t)M_ROWS * K_DIM];   // 256 MiB: [y_conv | y_auto]
__device__ float g_xm[M_ROWS];                     // per (b,l) channel mean
__device__ float g_w5[B_BATCH * 5];                // top-5 normalized weights
__device__ int   g_lag5[B_BATCH * 5];              // top-5 lags

// Candidate lag i of np.linspace(1,168,32).astype(int64)
__device__ __forceinline__ int lag_of(int i) {
    if (i == 31) return 168;                       // numpy sets endpoint exactly
    return (int)(1.0 + (double)i * (167.0 / 31.0));
}

// =================== Kernel 1: xm[b,l] = mean_d x[b,l,d] ===================
__global__ __launch_bounds__(256) void mean_kernel(const float* __restrict__ x) {
    int row  = blockIdx.x * 8 + (threadIdx.x >> 5);
    int lane = threadIdx.x & 31;
    const float4* xr = (const float4*)(x + (size_t)row * D_DIM);
    float s = 0.f;
#pragma unroll
    for (int q = 0; q < 4; q++) {
        float4 v = xr[q * 32 + lane];
        s += v.x + v.y + v.z + v.w;
    }
#pragma unroll
    for (int o = 16; o; o >>= 1) s += __shfl_down_sync(0xffffffffu, s, o);
    if (lane == 0) g_xm[row] = s * (1.0f / 512.0f);
}

// =============== Kernel 2: per-batch lag scores, top-5 weights ===============
__global__ __launch_bounds__(256) void scores_kernel() {
    __shared__ float s[L_SEQ];
    __shared__ float sc[32];
    int b = blockIdx.x, tid = threadIdx.x;
    for (int i = tid; i < L_SEQ; i += 256) s[i] = g_xm[b * L_SEQ + i];
    __syncthreads();
    int warp = tid >> 5, lane = tid & 31;
#pragma unroll
    for (int j = 0; j < 4; j++) {
        int li = warp * 4 + j;
        int lag = lag_of(li);
        float p = 0.f;
        for (int t = lane; t < L_SEQ - lag; t += 32) p += s[t] * s[t + lag];
#pragma unroll
        for (int o = 16; o; o >>= 1) p += __shfl_down_sync(0xffffffffu, p, o);
        if (lane == 0) sc[li] = p / (float)(L_SEQ - lag);
    }
    __syncthreads();
    if (tid == 0) {
        bool used[32];
        for (int i = 0; i < 32; i++) used[i] = false;
        float vals[5]; int idx[5];
        for (int p = 0; p < 5; p++) {
            float best = -3.4e38f; int bi = 0;
            for (int i = 0; i < 32; i++)
                if (!used[i] && sc[i] > best) { best = sc[i]; bi = i; }
            used[bi] = true; vals[p] = best; idx[p] = bi;
        }
        float denom = vals[0] + vals[1] + vals[2] + vals[3] + vals[4] + 1e-6f;
        for (int p = 0; p < 5; p++) {
            g_w5[b * 5 + p]   = vals[p] / denom;
            g_lag5[b * 5 + p] = lag_of(idx[p]);
        }
    }
}

// =============== Kernel 3: build ycat = [y_conv | y_auto] ===============
// block: (batch b, 32-row L tile); thread: 4 consecutive d + half the rows
__global__ __launch_bounds__(256) void ycat_kernel(
    const float* __restrict__ x,  const float* __restrict__ w0,
    const float* __restrict__ w1, const float* __restrict__ w2)
{
    const int OFF[11] = {-12, -8, -4, -2, -1, 0, 1, 2, 4, 8, 12};
    int b  = blockIdx.x >> 6;
    int lt = (blockIdx.x & 63) << 5;
    int tid = threadIdx.x;
    int d  = (tid & 127) << 2;
    int rh = tid >> 7;

    float cf[11][4];
#pragma unroll
    for (int c = 0; c < 4; c++) {
        int dd = d + c;
        float a0 = w0[dd * 3 + 0], a1 = w0[dd * 3 + 1], a2 = w0[dd * 3 + 2];
        float e0 = w1[dd * 5 + 0], e1 = w1[dd * 5 + 1], e2 = w1[dd * 5 + 2],
              e3 = w1[dd * 5 + 3], e4 = w1[dd * 5 + 4];
        float f0 = w2[dd * 7 + 0], f1 = w2[dd * 7 + 1], f2 = w2[dd * 7 + 2],
              f3 = w2[dd * 7 + 3], f4 = w2[dd * 7 + 4], f5 = w2[dd * 7 + 5],
              f6 = w2[dd * 7 + 6];
        cf[0][c]  = f0;            // -12
        cf[1][c]  = f1;            // -8
        cf[2][c]  = e0 + f2;       // -4
        cf[3][c]  = e1;            // -2
        cf[4][c]  = a0;            // -1
        cf[5][c]  = a1 + e2 + f3;  //  0
        cf[6][c]  = a2;            // +1
        cf[7][c]  = e3;            // +2
        cf[8][c]  = e4 + f4;       // +4
        cf[9][c]  = f5;            // +8
        cf[10][c] = f6;            // +12
    }
    float aw[5]; int al[5];
#pragma unroll
    for (int j = 0; j < 5; j++) { aw[j] = g_w5[b * 5 + j]; al[j] = g_lag5[b * 5 + j]; }

    const float* xb = x + ((size_t)b * L_SEQ) * D_DIM;
    for (int lidx = rh; lidx < 32; lidx += 2) {
        int l = lt + lidx;
        float ax = 0.f, ay = 0.f, az = 0.f, aq = 0.f;
#pragma unroll
        for (int o = 0; o < 11; o++) {
            int ll = l + OFF[o];
            if (ll >= 0 && ll < L_SEQ) {
                float4 xv = *(const float4*)(xb + (size_t)ll * D_DIM + d);
                ax += cf[o][0] * xv.x; ay += cf[o][1] * xv.y;
                az += cf[o][2] * xv.z; aq += cf[o][3] * xv.w;
            }
        }
        float ux = 0.f, uy = 0.f, uz = 0.f, uq = 0.f;
#pragma unroll
        for (int j = 0; j < 5; j++) {
            int ll = l - al[j]; if (ll < 0) ll += L_SEQ;
            float4 xv = *(const float4*)(xb + (size_t)ll * D_DIM + d);
            ux += aw[j] * xv.x; uy += aw[j] * xv.y;
            uz += aw[j] * xv.z; uq += aw[j] * xv.w;
        }
        size_t row = (size_t)b * L_SEQ + l;
        *(float4*)(g_ycat + row * K_DIM + d)       = make_float4(ax, ay, az, aq);
        *(float4*)(g_ycat + row * K_DIM + 512 + d) = make_float4(ux, uy, uz, uq);
    }
}

// =============== Kernel 4: tf32 MMA GEMM + (bias + residual) epilogue ===============
__device__ __forceinline__ uint32_t f2tf32(float f) {
    uint32_t r; asm("cvt.rna.tf32.f32 %0, %1;" : "=r"(r) : "f"(f)); return r;
}

__global__ __launch_bounds__(256) void gemm_ep_kernel(
    const float* __restrict__ x,   const float* __restrict__ Wn,  // [N][K] row-major
    const float* __restrict__ bias, float* __restrict__ out)
{
    __shared__ uint32_t As[2][128][20];   // [m][k], stride-20 pad (conflict-free frags)
    __shared__ uint32_t Bs[2][128][20];   // [n][k]
    const int tid  = threadIdx.x;
    const int m0   = blockIdx.y * 128;
    const int n0   = blockIdx.x * 128;
    const int warp = tid >> 5, lane = tid & 31;
    const int wm = (warp & 1) << 6;   // warp M offset (2 warps along M)
    const int wn = (warp >> 1) << 5;  // warp N offset (4 warps along N)
    const int gg = lane >> 2, tg = lane & 3;

    const float* Ag = g_ycat + (size_t)m0 * K_DIM;
    const float* Bg = Wn     + (size_t)n0 * K_DIM;

    const int r0 = tid >> 2;          // tile row 0..63 (and +64)
    const int kq = (tid & 3) << 2;    // k sub-offset 0,4,8,12

    float c[4][4][4];
#pragma unroll
    for (int mi = 0; mi < 4; mi++)
#pragma unroll
        for (int ni = 0; ni < 4; ni++)
#pragma unroll
            for (int q = 0; q < 4; q++) c[mi][ni][q] = 0.f;

    float4 ar0, ar1, br0, br1;
    ar0 = *(const float4*)(Ag + (size_t)r0 * K_DIM + kq);
    ar1 = *(const float4*)(Ag + (size_t)(r0 + 64) * K_DIM + kq);
    br0 = *(const float4*)(Bg + (size_t)r0 * K_DIM + kq);
    br1 = *(const float4*)(Bg + (size_t)(r0 + 64) * K_DIM + kq);
    *(uint4*)&As[0][r0][kq]      = make_uint4(f2tf32(ar0.x), f2tf32(ar0.y), f2tf32(ar0.z), f2tf32(ar0.w));
    *(uint4*)&As[0][r0 + 64][kq] = make_uint4(f2tf32(ar1.x), f2tf32(ar1.y), f2tf32(ar1.z), f2tf32(ar1.w));
    *(uint4*)&Bs[0][r0][kq]      = make_uint4(f2tf32(br0.x), f2tf32(br0.y), f2tf32(br0.z), f2tf32(br0.w));
    *(uint4*)&Bs[0][r0 + 64][kq] = make_uint4(f2tf32(br1.x), f2tf32(br1.y), f2tf32(br1.z), f2tf32(br1.w));
    __syncthreads();

    for (int kt = 0; kt < 64; ++kt) {
        int buf = kt & 1;
        if (kt < 63) {
            int k0 = (kt + 1) << 4;
            ar0 = *(const float4*)(Ag + (size_t)r0 * K_DIM + k0 + kq);
            ar1 = *(const float4*)(Ag + (size_t)(r0 + 64) * K_DIM + k0 + kq);
            br0 = *(const float4*)(Bg + (size_t)r0 * K_DIM + k0 + kq);
            br1 = *(const float4*)(Bg + (size_t)(r0 + 64) * K_DIM + k0 + kq);
        }
#pragma unroll
        for (int ks = 0; ks < 2; ++ks) {
            const int kk = ks << 3;
            uint32_t af[4][4], bf[4][2];
#pragma unroll
            for (int mi = 0; mi < 4; mi++) {
                int rr = wm + (mi << 4) + gg;
                af[mi][0] = As[buf][rr][kk + tg];
                af[mi][1] = As[buf][rr + 8][kk + tg];
                af[mi][2] = As[buf][rr][kk + tg + 4];
                af[mi][3] = As[buf][rr + 8][kk + tg + 4];
            }
#pragma unroll
            for (int ni = 0; ni < 4; ni++) {
                int cc = wn + (ni << 3) + gg;
                bf[ni][0] = Bs[buf][cc][kk + tg];
                bf[ni][1] = Bs[buf][cc][kk + tg + 4];
            }
#pragma unroll
            for (int mi = 0; mi < 4; mi++)
#pragma unroll
                for (int ni = 0; ni < 4; ni++)
                    asm volatile(
                        "mma.sync.aligned.m16n8k8.row.col.f32.tf32.tf32.f32 "
                        "{%0,%1,%2,%3}, {%4,%5,%6,%7}, {%8,%9}, {%0,%1,%2,%3};\n"
                        : "+f"(c[mi][ni][0]), "+f"(c[mi][ni][1]),
                          "+f"(c[mi][ni][2]), "+f"(c[mi][ni][3])
                        : "r"(af[mi][0]), "r"(af[mi][1]), "r"(af[mi][2]), "r"(af[mi][3]),
                          "r"(bf[ni][0]), "r"(bf[ni][1]));
        }
        if (kt < 63) {
            int nb = buf ^ 1;
            *(uint4*)&As[nb][r0][kq]      = make_uint4(f2tf32(ar0.x), f2tf32(ar0.y), f2tf32(ar0.z), f2tf32(ar0.w));
            *(uint4*)&As[nb][r0 + 64][kq] = make_uint4(f2tf32(ar1.x), f2tf32(ar1.y), f2tf32(ar1.z), f2tf32(ar1.w));
            *(uint4*)&Bs[nb][r0][kq]      = make_uint4(f2tf32(br0.x), f2tf32(br0.y), f2tf32(br0.z), f2tf32(br0.w));
            *(uint4*)&Bs[nb][r0 + 64][kq] = make_uint4(f2tf32(br1.x), f2tf32(br1.y), f2tf32(br1.z), f2tf32(br1.w));
            __syncthreads();
        }
    }

    // epilogue: h = gemm + bias + x  (LayerNorm runs as a separate pass)
#pragma unroll
    for (int mi = 0; mi < 4; mi++) {
        int row = m0 + wm + (mi << 4) + gg;
#pragma unroll
        for (int ni = 0; ni < 4; ni++) {
            int col = n0 + wn + (ni << 3) + (tg << 1);
            float bz0 = bias[col], bz1 = bias[col + 1];
            float2 x0 = *(const float2*)(x + (size_t)row * N_DIM + col);
            float2 x1 = *(const float2*)(x + (size_t)(row + 8) * N_DIM + col);
            float2 o0 = make_float2(c[mi][ni][0] + bz0 + x0.x, c[mi][ni][1] + bz1 + x0.y);
            float2 o1 = make_float2(c[mi][ni][2] + bz0 + x1.x, c[mi][ni][3] + bz1 + x1.y);
            *(float2*)(out + (size_t)row * N_DIM + col)       = o0;
            *(float2*)(out + (size_t)(row + 8) * N_DIM + col) = o1;
        }
    }
}

// =============== Kernel 5: LayerNorm over D, in place on out ===============
__global__ __launch_bounds__(256) void ln_kernel(
    float* __restrict__ out, const float* __restrict__ gam, const float* __restrict__ bet)
{
    int row  = blockIdx.x * 8 + (threadIdx.x >> 5);
    int lane = threadIdx.x & 31;
    float4* o4 = (float4*)(out + (size_t)row * D_DIM);
    float4 v[4];
    float s = 0.f, s2 = 0.f;
#pragma unroll
    for (int q = 0; q < 4; q++) {
        v[q] = o4[q * 32 + lane];
        s  += v[q].x + v[q].y + v[q].z + v[q].w;
        s2 += v[q].x * v[q].x + v[q].y * v[q].y + v[q].z * v[q].z + v[q].w * v[q].w;
    }
#pragma unroll
    for (int o = 16; o; o >>= 1) {
        s  += __shfl_xor_sync(0xffffffffu, s, o);
        s2 += __shfl_xor_sync(0xffffffffu, s2, o);
    }
    float mu  = s * (1.0f / 512.0f);
    float var = s2 * (1.0f / 512.0f) - mu * mu;
    float inv = rsqrtf(var + 1e-5f);
    const float4* g4 = (const float4*)gam;
    const float4* b4 = (const float4*)bet;
#pragma unroll
    for (int q = 0; q < 4; q++) {
        float4 gv = g4[q * 32 + lane], bv = b4[q * 32 + lane];
        float4 r;
        r.x = (v[q].x - mu) * inv * gv.x + bv.x;
        r.y = (v[q].y - mu) * inv * gv.y + bv.y;
        r.z = (v[q].z - mu) * inv * gv.z + bv.z;
        r.w = (v[q].w - mu) * inv * gv.w + bv.w;
        o4[q * 32 + lane] = r;
    }
}

// ============================== launch ==============================
extern "C" void kernel_launch(void* const* d_in, const int* in_sizes, int n_in,
                              void* d_out, int out_size) {
    const float* x   = (const float*)d_in[0];
    const float* cw0 = (const float*)d_in[1];
    const float* cw1 = (const float*)d_in[2];
    const float* cw2 = (const float*)d_in[3];
    const float* pw  = (const float*)d_in[4];
    const float* pb  = (const float*)d_in[5];
    const float* lng = (const float*)d_in[6];
    const float* lnb = (const float*)d_in[7];
    float* out = (float*)d_out;

    mean_kernel<<<M_ROWS / 8, 256>>>(x);
    scores_kernel<<<B_BATCH, 256>>>();
    ycat_kernel<<<B_BATCH * (L_SEQ / 32), 256>>>(x, cw0, cw1, cw2);
    dim3 ggrid(N_DIM / 128, M_ROWS / 128);   // n fastest -> A tiles shared in L2
    gemm_ep_kernel<<<ggrid, 256>>>(x, pw, pb, out);
    ln_kernel<<<M_ROWS / 8, 256>>>(out, lng, lnb);
}

// round 13
// speedup vs baseline: 1.6601x; 1.6601x over previous
#include <cuda_runtime.h>
#include <cstdint>

#define L_SEQ   2048
#define D_DIM   512
#define B_BATCH 32
#define M_ROWS  (B_BATCH * L_SEQ)   /* 65536 */
#define K_DIM   1024
#define N_DIM   512

// ---------------- scratch (static device globals: no allocation) ----------------
__device__ float g_ycat[(size_t)M_ROWS * K_DIM];   // 256 MiB: [y_conv | y_auto] (tf32-rounded)
__device__ float g_wr[(size_t)N_DIM * K_DIM];      // tf32-rounded proj_w
__device__ float g_xm[M_ROWS];
__device__ float g_w5[B_BATCH * 5];
__device__ int   g_lag5[B_BATCH * 5];

__device__ __forceinline__ uint32_t smem_to_u32(const void* p) {
    uint32_t a;
    asm("{ .reg .u64 t; cvta.to.shared.u64 t, %1; cvt.u32.u64 %0, t; }" : "=r"(a) : "l"(p));
    return a;
}
__device__ __forceinline__ float t32(float f) {
    uint32_t r; asm("cvt.rna.tf32.f32 %0, %1;" : "=r"(r) : "f"(f));
    return __uint_as_float(r);
}

// Candidate lag i of np.linspace(1,168,32).astype(int64)
__device__ __forceinline__ int lag_of(int i) {
    if (i == 31) return 168;
    return (int)(1.0 + (double)i * (167.0 / 31.0));
}

// =================== Kernel 1: xm[b,l] = mean_d x[b,l,d] ===================
__global__ __launch_bounds__(256) void mean_kernel(const float* __restrict__ x) {
    int row  = blockIdx.x * 8 + (threadIdx.x >> 5);
    int lane = threadIdx.x & 31;
    const float4* xr = (const float4*)(x + (size_t)row * D_DIM);
    float s = 0.f;
#pragma unroll
    for (int q = 0; q < 4; q++) {
        float4 v = xr[q * 32 + lane];
        s += v.x + v.y + v.z + v.w;
    }
#pragma unroll
    for (int o = 16; o; o >>= 1) s += __shfl_down_sync(0xffffffffu, s, o);
    if (lane == 0) g_xm[row] = s * (1.0f / 512.0f);
}

// =============== Kernel 2: per-batch lag scores, top-5 weights ===============
__global__ __launch_bounds__(256) void scores_kernel() {
    __shared__ float s[L_SEQ];
    __shared__ float sc[32];
    int b = blockIdx.x, tid = threadIdx.x;
    for (int i = tid; i < L_SEQ; i += 256) s[i] = g_xm[b * L_SEQ + i];
    __syncthreads();
    int warp = tid >> 5, lane = tid & 31;
#pragma unroll
    for (int j = 0; j < 4; j++) {
        int li = warp * 4 + j;
        int lag = lag_of(li);
        float p = 0.f;
        for (int t = lane; t < L_SEQ - lag; t += 32) p += s[t] * s[t + lag];
#pragma unroll
        for (int o = 16; o; o >>= 1) p += __shfl_down_sync(0xffffffffu, p, o);
        if (lane == 0) sc[li] = p / (float)(L_SEQ - lag);
    }
    __syncthreads();
    if (tid == 0) {
        bool used[32];
        for (int i = 0; i < 32; i++) used[i] = false;
        float vals[5]; int idx[5];
        for (int p = 0; p < 5; p++) {
            float best = -3.4e38f; int bi = 0;
            for (int i = 0; i < 32; i++)
                if (!used[i] && sc[i] > best) { best = sc[i]; bi = i; }
            used[bi] = true; vals[p] = best; idx[p] = bi;
        }
        float denom = vals[0] + vals[1] + vals[2] + vals[3] + vals[4] + 1e-6f;
        for (int p = 0; p < 5; p++) {
            g_w5[b * 5 + p]   = vals[p] / denom;
            g_lag5[b * 5 + p] = lag_of(idx[p]);
        }
    }
}

// =============== Kernel 2b: round proj_w to tf32 (rna) ===============
__global__ __launch_bounds__(256) void wround_kernel(const float* __restrict__ w) {
    size_t i = (size_t)blockIdx.x * 1024 + (size_t)threadIdx.x * 4;
    float4 v = *(const float4*)(w + i);
    *(float4*)(g_wr + i) = make_float4(t32(v.x), t32(v.y), t32(v.z), t32(v.w));
}

// =============== Kernel 3: build ycat = [y_conv | y_auto] (tf32-rounded) ===============
__global__ __launch_bounds__(256) void ycat_kernel(
    const float* __restrict__ x,  const float* __restrict__ w0,
    const float* __restrict__ w1, const float* __restrict__ w2)
{
    const int OFF[11] = {-12, -8, -4, -2, -1, 0, 1, 2, 4, 8, 12};
    int b  = blockIdx.x >> 6;
    int lt = (blockIdx.x & 63) << 5;
    int tid = threadIdx.x;
    int d  = (tid & 127) << 2;
    int rh = tid >> 7;

    float cf[11][4];
#pragma unroll
    for (int c = 0; c < 4; c++) {
        int dd = d + c;
        float a0 = w0[dd * 3 + 0], a1 = w0[dd * 3 + 1], a2 = w0[dd * 3 + 2];
        float e0 = w1[dd * 5 + 0], e1 = w1[dd * 5 + 1], e2 = w1[dd * 5 + 2],
              e3 = w1[dd * 5 + 3], e4 = w1[dd * 5 + 4];
        float f0 = w2[dd * 7 + 0], f1 = w2[dd * 7 + 1], f2 = w2[dd * 7 + 2],
              f3 = w2[dd * 7 + 3], f4 = w2[dd * 7 + 4], f5 = w2[dd * 7 + 5],
              f6 = w2[dd * 7 + 6];
        cf[0][c]  = f0;            cf[1][c]  = f1;            cf[2][c]  = e0 + f2;
        cf[3][c]  = e1;            cf[4][c]  = a0;            cf[5][c]  = a1 + e2 + f3;
        cf[6][c]  = a2;            cf[7][c]  = e3;            cf[8][c]  = e4 + f4;
        cf[9][c]  = f5;            cf[10][c] = f6;
    }
    float aw[5]; int al[5];
#pragma unroll
    for (int j = 0; j < 5; j++) { aw[j] = g_w5[b * 5 + j]; al[j] = g_lag5[b * 5 + j]; }

    const float* xb = x + ((size_t)b * L_SEQ) * D_DIM;
    for (int lidx = rh; lidx < 32; lidx += 2) {
        int l = lt + lidx;
        float ax = 0.f, ay = 0.f, az = 0.f, aq = 0.f;
#pragma unroll
        for (int o = 0; o < 11; o++) {
            int ll = l + OFF[o];
            if (ll >= 0 && ll < L_SEQ) {
                float4 xv = *(const float4*)(xb + (size_t)ll * D_DIM + d);
                ax += cf[o][0] * xv.x; ay += cf[o][1] * xv.y;
                az += cf[o][2] * xv.z; aq += cf[o][3] * xv.w;
            }
        }
        float ux = 0.f, uy = 0.f, uz = 0.f, uq = 0.f;
#pragma unroll
        for (int j = 0; j < 5; j++) {
            int ll = l - al[j]; if (ll < 0) ll += L_SEQ;
            float4 xv = *(const float4*)(xb + (size_t)ll * D_DIM + d);
            ux += aw[j] * xv.x; uy += aw[j] * xv.y;
            uz += aw[j] * xv.z; uq += aw[j] * xv.w;
        }
        size_t row = (size_t)b * L_SEQ + l;
        *(float4*)(g_ycat + row * K_DIM + d) =
            make_float4(t32(ax), t32(ay), t32(az), t32(aq));
        *(float4*)(g_ycat + row * K_DIM + 512 + d) =
            make_float4(t32(ux), t32(uy), t32(uz), t32(uq));
    }
}

// =============== Kernel 4: tf32 mma.sync GEMM, 128x128 block, 64x64 warp tile ===============
// 3-stage cp.async pipeline; operands pre-rounded to tf32 so staging is a raw copy.
#define BK 16
#define ROW_W 20                        /* padded row stride (words): conflict-free */
#define TILE_WORDS (128 * ROW_W)        /* 2560 words per A or B stage */
#define STAGE_WORDS (2 * TILE_WORDS)    /* A then B */
#define GEMM_SMEM (3 * STAGE_WORDS * 4) /* 61440 B */

__global__ void __launch_bounds__(128, 2) gemm_sm_kernel(
    const float* __restrict__ x, const float* __restrict__ bias, float* __restrict__ out)
{
    extern __shared__ uint32_t sm[];
    const int tid  = threadIdx.x;
    const int warp = tid >> 5, lane = tid & 31;
    const int gg = lane >> 2, tg = lane & 3;
    const int wm = (warp & 1) << 6;       // 2 warps along M
    const int wn = (warp >> 1) << 6;      // 2 warps along N, 64 wide each
    const int n0 = (int)(blockIdx.x & 3) << 7;   // n fastest: A tile L2-shared by 4 CTAs
    const int m0 = (int)(blockIdx.x >> 2) << 7;

    const float* Ag = g_ycat + (size_t)m0 * K_DIM;
    const float* Bg = g_wr   + (size_t)n0 * K_DIM;

    const uint32_t sbase = smem_to_u32(sm);
    const int r  = tid >> 2;              // staging row 0..31 (+32j)
    const int c4 = (tid & 3) << 2;        // staging col 0,4,8,12

    float acc[4][8][4];
#pragma unroll
    for (int mi = 0; mi < 4; mi++)
#pragma unroll
        for (int ni = 0; ni < 8; ni++)
#pragma unroll
            for (int q = 0; q < 4; q++) acc[mi][ni][q] = 0.f;

    auto stage_load = [&](int kt, int s) {
        const float* ag = Ag + kt * BK;
        const float* bg = Bg + kt * BK;
        uint32_t sa = sbase + (uint32_t)(s * STAGE_WORDS) * 4u;
        uint32_t sb = sa + TILE_WORDS * 4u;
#pragma unroll
        for (int j = 0; j < 4; j++) {
            int rr = r + (j << 5);
            uint32_t off = (uint32_t)(rr * ROW_W + c4) * 4u;
            asm volatile("cp.async.cg.shared.global [%0], [%1], 16;"
                         :: "r"(sa + off), "l"(ag + (size_t)rr * K_DIM + c4));
            asm volatile("cp.async.cg.shared.global [%0], [%1], 16;"
                         :: "r"(sb + off), "l"(bg + (size_t)rr * K_DIM + c4));
        }
        asm volatile("cp.async.commit_group;" ::: "memory");
    };

    stage_load(0, 0); stage_load(1, 1); stage_load(2, 2);

#pragma unroll 1
    for (int kt = 0; kt < 64; kt++) {
        const int s = kt % 3;
        asm volatile("cp.async.wait_group 2;" ::: "memory");
        __syncthreads();
        const uint32_t* As = sm + s * STAGE_WORDS;
        const uint32_t* Bs = As + TILE_WORDS;
#pragma unroll
        for (int ks = 0; ks < 2; ks++) {
            const int kk = ks << 3;
            uint32_t a[4][4], b[8][2];
#pragma unroll
            for (int mi = 0; mi < 4; mi++) {
                int rr = wm + (mi << 4) + gg;
                a[mi][0] = As[rr * ROW_W + kk + tg];
                a[mi][1] = As[(rr + 8) * ROW_W + kk + tg];
                a[mi][2] = As[rr * ROW_W + kk + tg + 4];
                a[mi][3] = As[(rr + 8) * ROW_W + kk + tg + 4];
            }
#pragma unroll
            for (int ni = 0; ni < 8; ni++) {
                int cc = wn + (ni << 3) + gg;
                b[ni][0] = Bs[cc * ROW_W + kk + tg];
                b[ni][1] = Bs[cc * ROW_W + kk + tg + 4];
            }
#pragma unroll
            for (int mi = 0; mi < 4; mi++)
#pragma unroll
                for (int ni = 0; ni < 8; ni++)
                    asm volatile(
                        "mma.sync.aligned.m16n8k8.row.col.f32.tf32.tf32.f32 "
                        "{%0,%1,%2,%3}, {%4,%5,%6,%7}, {%8,%9}, {%0,%1,%2,%3};\n"
                        : "+f"(acc[mi][ni][0]), "+f"(acc[mi][ni][1]),
                          "+f"(acc[mi][ni][2]), "+f"(acc[mi][ni][3])
                        : "r"(a[mi][0]), "r"(a[mi][1]), "r"(a[mi][2]), "r"(a[mi][3]),
                          "r"(b[ni][0]), "r"(b[ni][1]));
        }
        __syncthreads();
        if (kt + 3 < 64) stage_load(kt + 3, s);
        else asm volatile("cp.async.commit_group;" ::: "memory");  // keep group count aligned
    }

    // epilogue: h = gemm + bias + x
#pragma unroll
    for (int mi = 0; mi < 4; mi++) {
        int row = m0 + wm + (mi << 4) + gg;
#pragma unroll
        for (int ni = 0; ni < 8; ni++) {
            int col = n0 + wn + (ni << 3) + (tg << 1);
            float bz0 = bias[col], bz1 = bias[col + 1];
            float2 x0 = *(const float2*)(x + (size_t)row * N_DIM + col);
            float2 x1 = *(const float2*)(x + (size_t)(row + 8) * N_DIM + col);
            float2 o0 = make_float2(acc[mi][ni][0] + bz0 + x0.x, acc[mi][ni][1] + bz1 + x0.y);
            float2 o1 = make_float2(acc[mi][ni][2] + bz0 + x1.x, acc[mi][ni][3] + bz1 + x1.y);
            *(float2*)(out + (size_t)row * N_DIM + col)       = o0;
            *(float2*)(out + (size_t)(row + 8) * N_DIM + col) = o1;
        }
    }
}

// =============== Kernel 5: LayerNorm over D, in place on out ===============
__global__ __launch_bounds__(256) void ln_kernel(
    float* __restrict__ out, const float* __restrict__ gam, const float* __restrict__ bet)
{
    int row  = blockIdx.x * 8 + (threadIdx.x >> 5);
    int lane = threadIdx.x & 31;
    float4* o4 = (float4*)(out + (size_t)row * D_DIM);
    float4 v[4];
    float s = 0.f, s2 = 0.f;
#pragma unroll
    for (int q = 0; q < 4; q++) {
        v[q] = o4[q * 32 + lane];
        s  += v[q].x + v[q].y + v[q].z + v[q].w;
        s2 += v[q].x * v[q].x + v[q].y * v[q].y + v[q].z * v[q].z + v[q].w * v[q].w;
    }
#pragma unroll
    for (int o = 16; o; o >>= 1) {
        s  += __shfl_xor_sync(0xffffffffu, s, o);
        s2 += __shfl_xor_sync(0xffffffffu, s2, o);
    }
    float mu  = s * (1.0f / 512.0f);
    float var = s2 * (1.0f / 512.0f) - mu * mu;
    float inv = rsqrtf(var + 1e-5f);
    const float4* g4 = (const float4*)gam;
    const float4* b4 = (const float4*)bet;
#pragma unroll
    for (int q = 0; q < 4; q++) {
        float4 gv = g4[q * 32 + lane], bv = b4[q * 32 + lane];
        float4 r;
        r.x = (v[q].x - mu) * inv * gv.x + bv.x;
        r.y = (v[q].y - mu) * inv * gv.y + bv.y;
        r.z = (v[q].z - mu) * inv * gv.z + bv.z;
        r.w = (v[q].w - mu) * inv * gv.w + bv.w;
        o4[q * 32 + lane] = r;
    }
}

// ============================== launch ==============================
extern "C" void kernel_launch(void* const* d_in, const int* in_sizes, int n_in,
                              void* d_out, int out_size) {
    const float* x   = (const float*)d_in[0];
    const float* cw0 = (const float*)d_in[1];
    const float* cw1 = (const float*)d_in[2];
    const float* cw2 = (const float*)d_in[3];
    const float* pw  = (const float*)d_in[4];
    const float* pb  = (const float*)d_in[5];
    const float* lng = (const float*)d_in[6];
    const float* lnb = (const float*)d_in[7];
    float* out = (float*)d_out;

    cudaFuncSetAttribute(gemm_sm_kernel,
                         cudaFuncAttributeMaxDynamicSharedMemorySize, GEMM_SMEM);

    mean_kernel<<<M_ROWS / 8, 256>>>(x);
    scores_kernel<<<B_BATCH, 256>>>();
    wround_kernel<<<(N_DIM * K_DIM) / 1024, 256>>>(pw);
    ycat_kernel<<<B_BATCH * (L_SEQ / 32), 256>>>(x, cw0, cw1, cw2);
    gemm_sm_kernel<<<(M_ROWS / 128) * (N_DIM / 128), 128, GEMM_SMEM>>>(x, pb, out);
    ln_kernel<<<M_ROWS / 8, 256>>>(out, lng, lnb);
}